// round 4
// baseline (speedup 1.0000x reference)
#include <cuda_runtime.h>
#include <cmath>

// Problem constants
#define B_ 2
#define S_ 1024
#define D_ 1024
#define H_ 16
#define L_ 4
#define DH_ 64
#define BH_ (B_ * H_)
#define M_ (B_ * S_)   // 2048 rows

typedef unsigned long long u64;

// ---------------- scratch (device globals; allocation-free) ----------------
__device__ __align__(16) float g_x [(size_t)B_ * S_ * D_];   // current residual stream x
__device__ __align__(16) float g_q [(size_t)B_ * S_ * D_];   // Q (=K) projection
__device__ __align__(16) float g_v [(size_t)B_ * S_ * D_];   // V projection
__device__ __align__(16) float g_ao[(size_t)B_ * S_ * D_];   // attn output pre-Wo
__device__ __align__(16) float g_pr[(size_t)B_ * S_ * D_];   // Wo projection output
__device__ __align__(16) float g_sc[(size_t)B_ * H_ * S_ * S_]; // scores/attn scratch (134MB)

// ---------------- packed f32x2 helpers (sm_100+) ----------------
__device__ __forceinline__ void fma2(u64& d, u64 a, u64 b) {
    asm("fma.rn.f32x2 %0, %1, %2, %0;" : "+l"(d) : "l"(a), "l"(b));
}
__device__ __forceinline__ u64 pack2(float lo, float hi) {
    u64 r;
    asm("mov.b64 %0, {%1, %2};" : "=l"(r) : "f"(lo), "f"(hi));
    return r;
}
__device__ __forceinline__ void unpack2(u64 v, float& lo, float& hi) {
    asm("mov.b64 {%0, %1}, %2;" : "=f"(lo), "=f"(hi) : "l"(v));
}

// ---------------- warp reduction helpers ----------------
__device__ __forceinline__ float warp_max(float v) {
#pragma unroll
    for (int o = 16; o > 0; o >>= 1) v = fmaxf(v, __shfl_xor_sync(0xffffffffu, v, o));
    return v;
}
__device__ __forceinline__ float warp_sum(float v) {
#pragma unroll
    for (int o = 16; o > 0; o >>= 1) v += __shfl_xor_sync(0xffffffffu, v, o);
    return v;
}
__device__ __forceinline__ float warp_iscan(float v, int lane) {
#pragma unroll
    for (int o = 1; o < 32; o <<= 1) {
        float u = __shfl_up_sync(0xffffffffu, v, o);
        if (lane >= o) v += u;
    }
    return v;
}

// ---------------- input copy: q -> g_x ----------------
__global__ void copy_in_kernel(const float4* __restrict__ src) {
    size_t i = (size_t)blockIdx.x * 256 + threadIdx.x;
    reinterpret_cast<float4*>(g_x)[i] = src[i];
}

// ---------------- projection GEMM: C = A(2048x1024) @ W(1024x1024) + bias --------
// sel: 0 -> A=g_x, C=g_q ; 1 -> A=g_x, C=g_v ; 2 -> A=g_ao, C=g_pr
// 128x128 tile, BK=16, 256 threads, 8x8 per thread, packed FFMA2 inner loop,
// register double-buffered global loads.
__global__ void __launch_bounds__(256) gemm_bias_kernel(int sel,
                                                        const float* __restrict__ W,
                                                        const float* __restrict__ bias) {
    const float* A = (sel == 2) ? g_ao : g_x;
    float* C = (sel == 0) ? g_q : ((sel == 1) ? g_v : g_pr);

    __shared__ float As[16][128];
    __shared__ float Bs[16][128];

    int bx = blockIdx.x;           // N tile (8)
    int by = blockIdx.y;           // M tile (16)
    int tid = threadIdx.x;
    int tx = tid & 15, ty = tid >> 4;

    const float* Ab = A + (size_t)by * 128 * D_;
    const float* Wb = W + (size_t)bx * 128;

    // per-thread load coordinates (2 float4 each for A and B tiles)
    int agr[2], agk[2], bgr[2], bgc[2];
#pragma unroll
    for (int r = 0; r < 2; r++) {
        int gA = tid + r * 256;     // 0..511
        agr[r] = gA >> 2;           // A row 0..127
        agk[r] = (gA & 3) * 4;      // A k sub-offset
        bgr[r] = gA >> 5;           // B row 0..15
        bgc[r] = (gA & 31) * 4;     // B col
    }

    u64 acc[8][4];
#pragma unroll
    for (int i = 0; i < 8; i++)
#pragma unroll
        for (int j = 0; j < 4; j++) acc[i][j] = 0ull;

    float4 pa[2], pb[2];
    // preload k0 = 0
#pragma unroll
    for (int r = 0; r < 2; r++) {
        pa[r] = *(const float4*)(Ab + (size_t)agr[r] * D_ + agk[r]);
        pb[r] = *(const float4*)(Wb + (size_t)bgr[r] * D_ + bgc[r]);
    }
#pragma unroll
    for (int r = 0; r < 2; r++) {
        As[agk[r] + 0][agr[r]] = pa[r].x;
        As[agk[r] + 1][agr[r]] = pa[r].y;
        As[agk[r] + 2][agr[r]] = pa[r].z;
        As[agk[r] + 3][agr[r]] = pa[r].w;
        *(float4*)&Bs[bgr[r]][bgc[r]] = pb[r];
    }
    __syncthreads();

    for (int k0 = 0; k0 < D_; k0 += 16) {
        int kn = k0 + 16;
        if (kn < D_) {
            // issue next tile's global loads early (overlap with compute)
#pragma unroll
            for (int r = 0; r < 2; r++) {
                pa[r] = *(const float4*)(Ab + (size_t)agr[r] * D_ + kn + agk[r]);
                pb[r] = *(const float4*)(Wb + (size_t)(kn + bgr[r]) * D_ + bgc[r]);
            }
        }
#pragma unroll
        for (int k = 0; k < 16; k++) {
            float4 ra0 = *(const float4*)&As[k][ty * 8];
            float4 ra1 = *(const float4*)&As[k][ty * 8 + 4];
            const u64* rbp = (const u64*)&Bs[k][tx * 8];
            u64 rb[4] = {rbp[0], rbp[1], rbp[2], rbp[3]};
            float ra[8] = {ra0.x, ra0.y, ra0.z, ra0.w, ra1.x, ra1.y, ra1.z, ra1.w};
#pragma unroll
            for (int i = 0; i < 8; i++) {
                u64 ad = pack2(ra[i], ra[i]);
#pragma unroll
                for (int j = 0; j < 4; j++) fma2(acc[i][j], ad, rb[j]);
            }
        }
        __syncthreads();
        if (kn < D_) {
#pragma unroll
            for (int r = 0; r < 2; r++) {
                As[agk[r] + 0][agr[r]] = pa[r].x;
                As[agk[r] + 1][agr[r]] = pa[r].y;
                As[agk[r] + 2][agr[r]] = pa[r].z;
                As[agk[r] + 3][agr[r]] = pa[r].w;
                *(float4*)&Bs[bgr[r]][bgc[r]] = pb[r];
            }
            __syncthreads();
        }
    }

#pragma unroll
    for (int i = 0; i < 8; i++) {
        int row = by * 128 + ty * 8 + i;
#pragma unroll
        for (int j = 0; j < 2; j++) {
            int col = bx * 128 + tx * 8 + j * 4;
            float a0, a1, a2, a3;
            unpack2(acc[i][j * 2 + 0], a0, a1);
            unpack2(acc[i][j * 2 + 1], a2, a3);
            float4 v;
            v.x = a0 + bias[col + 0];
            v.y = a1 + bias[col + 1];
            v.z = a2 + bias[col + 2];
            v.w = a3 + bias[col + 3];
            *(float4*)(C + (size_t)row * D_ + col) = v;
        }
    }
}

// ---------------- scores: g_sc[bh][i][j] = dot(Qh_i, Qh_j)/8, lower tiles only ----
__global__ void __launch_bounds__(256) scores_kernel() {
    int jt = blockIdx.x;   // key tile
    int it = blockIdx.y;   // query tile
    int bh = blockIdx.z;
    if (jt > it) return;   // strictly-causal: only j <= i tiles needed

    int b = bh / H_, h = bh % H_;
    const float* Qb = g_q + (size_t)b * S_ * D_ + h * DH_;

    __shared__ float As[64][64];  // [k][i]
    __shared__ float Bs[64][64];  // [k][j]

    int tid = threadIdx.x;
#pragma unroll
    for (int r = 0; r < 4; r++) {
        int g = tid + r * 256;    // 0..1023
        int row = g >> 4;         // 0..63
        int kq = g & 15;          // k/4
        float4 va = *(const float4*)(Qb + (size_t)(it * 64 + row) * D_ + kq * 4);
        As[kq * 4 + 0][row] = va.x; As[kq * 4 + 1][row] = va.y;
        As[kq * 4 + 2][row] = va.z; As[kq * 4 + 3][row] = va.w;
        float4 vb = *(const float4*)(Qb + (size_t)(jt * 64 + row) * D_ + kq * 4);
        Bs[kq * 4 + 0][row] = vb.x; Bs[kq * 4 + 1][row] = vb.y;
        Bs[kq * 4 + 2][row] = vb.z; Bs[kq * 4 + 3][row] = vb.w;
    }
    __syncthreads();

    int tx = tid & 15, ty = tid >> 4;
    u64 acc[4][2];
#pragma unroll
    for (int i = 0; i < 4; i++) { acc[i][0] = 0ull; acc[i][1] = 0ull; }

#pragma unroll 8
    for (int k = 0; k < 64; k++) {
        float4 ra = *(const float4*)&As[k][ty * 4];
        const u64* rbp = (const u64*)&Bs[k][tx * 4];
        u64 rb0 = rbp[0], rb1 = rbp[1];
        float rav[4] = {ra.x, ra.y, ra.z, ra.w};
#pragma unroll
        for (int i = 0; i < 4; i++) {
            u64 ad = pack2(rav[i], rav[i]);
            fma2(acc[i][0], ad, rb0);
            fma2(acc[i][1], ad, rb1);
        }
    }

    float* out = g_sc + (size_t)bh * S_ * S_;
#pragma unroll
    for (int i = 0; i < 4; i++) {
        int row = it * 64 + ty * 4 + i;
        float a0, a1, a2, a3;
        unpack2(acc[i][0], a0, a1);
        unpack2(acc[i][1], a2, a3);
        float4 v = {a0 * 0.125f, a1 * 0.125f, a2 * 0.125f, a3 * 0.125f};
        *(float4*)(out + (size_t)row * S_ + jt * 64 + tx * 4) = v;
    }
}

// ---------------- per-row gamma-attention pipeline (warp per row) ----------------
// Each warp owns one (bh, q) row of 1024 scores. Thread owns contiguous 32-elem
// chunk (one 128B line). All reductions are shuffles; no __syncthreads.
__global__ void __launch_bounds__(256) row_kernel(const float* __restrict__ gammas, int layer) {
    int warp = threadIdx.x >> 5, lane = threadIdx.x & 31;
    int q = blockIdx.x * 8 + warp;     // 0..1023
    int bh = blockIdx.y;
    int h = bh % H_;
    float* rowp = g_sc + (size_t)bh * S_ * S_ + (size_t)q * S_;
    float* chunk = rowp + lane * 32;

    if (q == 0) {                      // fully-masked row -> attn = 0
        float4 z = {0.f, 0.f, 0.f, 0.f};
#pragma unroll
        for (int i = 0; i < 8; i++) *(float4*)(chunk + i * 4) = z;
        return;
    }

    int kbase = lane * 32;
    float s[32];
#pragma unroll
    for (int i = 0; i < 8; i++) {
        float4 v = *(const float4*)(chunk + i * 4);
        s[i * 4 + 0] = v.x; s[i * 4 + 1] = v.y; s[i * 4 + 2] = v.z; s[i * 4 + 3] = v.w;
    }

    // ---- first masked softmax (unnormalized e, denom) ----
    float lmax = -INFINITY;
#pragma unroll
    for (int i = 0; i < 32; i++)
        if (kbase + i < q) lmax = fmaxf(lmax, s[i]);
    float m1 = warp_max(lmax);

    float e[32];
    float lsum = 0.f;
#pragma unroll
    for (int i = 0; i < 32; i++) {
        e[i] = (kbase + i < q) ? expf(s[i] - m1) : 0.f;
        lsum += e[i];
    }
    float denom = warp_sum(lsum);
    float inv_denom = 1.0f / denom;

    // ---- inclusive cumsum of e across the row (local scan + warp offset) ----
    float incl = warp_iscan(lsum, lane);
    float excl = incl - lsum;
    float tot_e = __shfl_sync(0xffffffffu, incl, 31);
    float total = tot_e * inv_denom;   // == sum(p)

    // ---- distance decay + second softmax input ----
    float g = -fabsf(gammas[layer * H_ + h]);
    float run = excl;
    float lmax2 = -INFINITY;
#pragma unroll
    for (int i = 0; i < 32; i++) {
        run += e[i];
        int k = kbase + i;
        float cum = run * inv_denom;                   // cumsum(p) inclusive
        float dd = fabsf((float)(q - k));
        float dist = sqrtf(fmaxf((total - cum) * dd, 0.f));
        float eff = expf(dist * g);
        eff = fminf(fmaxf(eff, 1e-5f), 1e5f);
        float s2 = (k < q) ? s[i] * eff : -INFINITY;
        s[i] = s2;
        lmax2 = fmaxf(lmax2, s2);
    }
    float m2 = warp_max(lmax2);

    float lsum2 = 0.f;
#pragma unroll
    for (int i = 0; i < 32; i++) {
        e[i] = (kbase + i < q) ? expf(s[i] - m2) : 0.f;
        lsum2 += e[i];
    }
    float d2 = warp_sum(lsum2);
    float inv_d2 = 1.0f / d2;

    // ---- maxout rescale: a = e/d2; scale = min(1/max(a), 5) ----
    float lamax = 0.f;
#pragma unroll
    for (int i = 0; i < 32; i++) lamax = fmaxf(lamax, e[i]);
    float amax = warp_max(lamax) * inv_d2;
    float scale = fminf(1.0f / amax, 5.0f) * inv_d2;

#pragma unroll
    for (int i = 0; i < 8; i++) {
        float4 v;
        v.x = e[i * 4 + 0] * scale;
        v.y = e[i * 4 + 1] * scale;
        v.z = e[i * 4 + 2] * scale;
        v.w = e[i * 4 + 3] * scale;
        *(float4*)(chunk + i * 4) = v;
    }
}

// ---------------- PV: g_ao[b, i, h*64+d] = sum_k attn[bh][i][k] * Vh[k][d] --------
// Register double-buffered over kt tiles.
__global__ void __launch_bounds__(256) pv_kernel() {
    int it = blockIdx.x;   // query row tile (16)
    int bh = blockIdx.y;
    int b = bh / H_, h = bh % H_;
    const float* att = g_sc + (size_t)bh * S_ * S_;
    const float* Vb = g_v + (size_t)b * S_ * D_ + h * DH_;
    float* Ob = g_ao + (size_t)b * S_ * D_ + h * DH_;

    __shared__ float As[64][64];  // attn transposed: [k][i]
    __shared__ float Bs[64][64];  // V: [k][d]

    int tid = threadIdx.x, tx = tid & 15, ty = tid >> 4;

    // load coordinates: 4 float4 per tile per array
    int lrow[4], lcq[4];
#pragma unroll
    for (int r = 0; r < 4; r++) {
        int g = tid + r * 256;
        lrow[r] = g >> 4;      // 0..63
        lcq[r] = (g & 15) * 4; // col offset
    }

    u64 acc[4][2];
#pragma unroll
    for (int i = 0; i < 4; i++) { acc[i][0] = 0ull; acc[i][1] = 0ull; }

    float4 va[4], vb[4];
    // preload kt = 0
#pragma unroll
    for (int r = 0; r < 4; r++) {
        va[r] = *(const float4*)(att + (size_t)(it * 64 + lrow[r]) * S_ + lcq[r]);
        vb[r] = *(const float4*)(Vb + (size_t)lrow[r] * D_ + lcq[r]);
    }
#pragma unroll
    for (int r = 0; r < 4; r++) {
        As[lcq[r] + 0][lrow[r]] = va[r].x; As[lcq[r] + 1][lrow[r]] = va[r].y;
        As[lcq[r] + 2][lrow[r]] = va[r].z; As[lcq[r] + 3][lrow[r]] = va[r].w;
        *(float4*)&Bs[lrow[r]][lcq[r]] = vb[r];
    }
    __syncthreads();

    // causal: attn[i][k]==0 for k > i, so only chunks kt <= it contribute
    for (int kt = 0; kt <= it; kt++) {
        if (kt + 1 <= it) {
#pragma unroll
            for (int r = 0; r < 4; r++) {
                va[r] = *(const float4*)(att + (size_t)(it * 64 + lrow[r]) * S_ + (kt + 1) * 64 + lcq[r]);
                vb[r] = *(const float4*)(Vb + (size_t)((kt + 1) * 64 + lrow[r]) * D_ + lcq[r]);
            }
        }
#pragma unroll 8
        for (int k = 0; k < 64; k++) {
            float4 ra = *(const float4*)&As[k][ty * 4];
            const u64* rbp = (const u64*)&Bs[k][tx * 4];
            u64 rb0 = rbp[0], rb1 = rbp[1];
            float rav[4] = {ra.x, ra.y, ra.z, ra.w};
#pragma unroll
            for (int i = 0; i < 4; i++) {
                u64 ad = pack2(rav[i], rav[i]);
                fma2(acc[i][0], ad, rb0);
                fma2(acc[i][1], ad, rb1);
            }
        }
        __syncthreads();
        if (kt + 1 <= it) {
#pragma unroll
            for (int r = 0; r < 4; r++) {
                As[lcq[r] + 0][lrow[r]] = va[r].x; As[lcq[r] + 1][lrow[r]] = va[r].y;
                As[lcq[r] + 2][lrow[r]] = va[r].z; As[lcq[r] + 3][lrow[r]] = va[r].w;
                *(float4*)&Bs[lrow[r]][lcq[r]] = vb[r];
            }
            __syncthreads();
        }
    }

#pragma unroll
    for (int i = 0; i < 4; i++) {
        float a0, a1, a2, a3;
        unpack2(acc[i][0], a0, a1);
        unpack2(acc[i][1], a2, a3);
        float4 v = {a0, a1, a2, a3};
        *(float4*)(Ob + (size_t)(it * 64 + ty * 4 + i) * D_ + tx * 4) = v;
    }
}

// ---------------- (x [+ g_pr]) -> LayerNorm -> (g_x | out) ----------------
// addA=1: v = g_x + g_pr, write g_x.  addA=0: v = g_x, write `out`.
__global__ void __launch_bounds__(256) ln_kernel(const float* __restrict__ gw,
                                                 const float* __restrict__ bw,
                                                 float* __restrict__ out, int addA) {
    int row = blockIdx.x;
    int t = threadIdx.x;
    int lane = t & 31, wid = t >> 5;
    __shared__ float red[33];

    float4 xv = *(const float4*)(g_x + (size_t)row * D_ + t * 4);
    float v0 = xv.x, v1 = xv.y, v2 = xv.z, v3 = xv.w;
    if (addA) {
        float4 av = *(const float4*)(g_pr + (size_t)row * D_ + t * 4);
        v0 += av.x; v1 += av.y; v2 += av.z; v3 += av.w;
    }
    float ssum = warp_sum(v0 + v1 + v2 + v3);
    if (lane == 0) red[wid] = ssum;
    __syncthreads();
    if (wid == 0) {
        float u = (lane < 8) ? red[lane] : 0.0f;
        u = warp_sum(u);
        if (lane == 0) red[32] = u;
    }
    __syncthreads();
    float mu = red[32] * (1.0f / D_);
    __syncthreads();

    float d0 = v0 - mu, d1 = v1 - mu, d2 = v2 - mu, d3 = v3 - mu;
    float vs = warp_sum(d0 * d0 + d1 * d1 + d2 * d2 + d3 * d3);
    if (lane == 0) red[wid] = vs;
    __syncthreads();
    if (wid == 0) {
        float u = (lane < 8) ? red[lane] : 0.0f;
        u = warp_sum(u);
        if (lane == 0) red[32] = u;
    }
    __syncthreads();
    float var = red[32] * (1.0f / D_);
    float rs = rsqrtf(var + 1e-5f);

    float4 g4 = *(const float4*)(gw + t * 4);
    float4 b4 = *(const float4*)(bw + t * 4);
    float4 o;
    o.x = d0 * rs * g4.x + b4.x;
    o.y = d1 * rs * g4.y + b4.y;
    o.z = d2 * rs * g4.z + b4.z;
    o.w = d3 * rs * g4.w + b4.w;
    float* dst = addA ? g_x : out;
    *(float4*)(dst + (size_t)row * D_ + t * 4) = o;
}

// ---------------- launch ----------------
extern "C" void kernel_launch(void* const* d_in, const int* in_sizes, int n_in,
                              void* d_out, int out_size) {
    (void)in_sizes; (void)n_in; (void)out_size;
    const float* q      = (const float*)d_in[0];
    // d_in[1] = lens (unused in eval mode)
    const float* Wq     = (const float*)d_in[2];
    const float* bq     = (const float*)d_in[3];
    const float* Wv     = (const float*)d_in[4];
    const float* bv     = (const float*)d_in[5];
    const float* Wo     = (const float*)d_in[6];
    const float* bo     = (const float*)d_in[7];
    const float* gammas = (const float*)d_in[8];
    const float* ln_g   = (const float*)d_in[9];
    const float* ln_b   = (const float*)d_in[10];
    const float* fin_g  = (const float*)d_in[11];
    const float* fin_b  = (const float*)d_in[12];

    // x = q
    copy_in_kernel<<<(M_ * D_ / 4) / 256, 256>>>((const float4*)q);

    dim3 gemm_grid(D_ / 128, M_ / 128);     // (8, 16)
    for (int l = 0; l < L_; l++) {
        size_t wOff = (size_t)l * D_ * D_;
        gemm_bias_kernel<<<gemm_grid, 256>>>(0, Wq + wOff, bq + (size_t)l * D_);
        gemm_bias_kernel<<<gemm_grid, 256>>>(1, Wv + wOff, bv + (size_t)l * D_);
        scores_kernel<<<dim3(S_ / 64, S_ / 64, BH_), 256>>>();
        row_kernel<<<dim3(S_ / 8, BH_), 256>>>(gammas, l);
        pv_kernel<<<dim3(S_ / 64, BH_), 256>>>();
        gemm_bias_kernel<<<gemm_grid, 256>>>(2, Wo + wOff, bo + (size_t)l * D_);
        ln_kernel<<<M_, 256>>>(ln_g + (size_t)l * D_, ln_b + (size_t)l * D_, nullptr, 1);
    }
    // final layer norm -> output
    ln_kernel<<<M_, 256>>>(fin_g, fin_b, (float*)d_out, 0);
}

// round 5
// speedup vs baseline: 1.0312x; 1.0312x over previous
#include <cuda_runtime.h>
#include <cmath>

// Problem constants
#define B_ 2
#define S_ 1024
#define D_ 1024
#define H_ 16
#define L_ 4
#define DH_ 64
#define BH_ (B_ * H_)
#define M_ (B_ * S_)   // 2048 rows

typedef unsigned long long u64;

// ---------------- scratch (device globals; allocation-free) ----------------
__device__ __align__(16) float g_x [(size_t)B_ * S_ * D_];   // current residual stream x
__device__ __align__(16) float g_q [(size_t)B_ * S_ * D_];   // Q (=K) projection
__device__ __align__(16) float g_v [(size_t)B_ * S_ * D_];   // V projection
__device__ __align__(16) float g_ao[(size_t)B_ * S_ * D_];   // attn output pre-Wo
__device__ __align__(16) float g_pr[(size_t)B_ * S_ * D_];   // Wo projection output
__device__ __align__(16) float g_sc[(size_t)B_ * H_ * S_ * S_]; // scores/attn scratch (134MB)

// ---------------- packed f32x2 helpers (sm_100+) ----------------
__device__ __forceinline__ void fma2(u64& d, u64 a, u64 b) {
    asm("fma.rn.f32x2 %0, %1, %2, %0;" : "+l"(d) : "l"(a), "l"(b));
}
__device__ __forceinline__ u64 pack2(float lo, float hi) {
    u64 r;
    asm("mov.b64 %0, {%1, %2};" : "=l"(r) : "f"(lo), "f"(hi));
    return r;
}
__device__ __forceinline__ void unpack2(u64 v, float& lo, float& hi) {
    asm("mov.b64 {%0, %1}, %2;" : "=f"(lo), "=f"(hi) : "l"(v));
}

// ---------------- warp reduction helpers ----------------
__device__ __forceinline__ float warp_max(float v) {
#pragma unroll
    for (int o = 16; o > 0; o >>= 1) v = fmaxf(v, __shfl_xor_sync(0xffffffffu, v, o));
    return v;
}
__device__ __forceinline__ float warp_sum(float v) {
#pragma unroll
    for (int o = 16; o > 0; o >>= 1) v += __shfl_xor_sync(0xffffffffu, v, o);
    return v;
}
__device__ __forceinline__ float warp_iscan(float v, int lane) {
#pragma unroll
    for (int o = 1; o < 32; o <<= 1) {
        float u = __shfl_up_sync(0xffffffffu, v, o);
        if (lane >= o) v += u;
    }
    return v;
}

// ---------------- input copy: q -> g_x ----------------
__global__ void copy_in_kernel(const float4* __restrict__ src) {
    size_t i = (size_t)blockIdx.x * 256 + threadIdx.x;
    reinterpret_cast<float4*>(g_x)[i] = src[i];
}

// ---------------- projection GEMM: C = A(2048x1024) @ W(1024x1024) + bias --------
// sel: 0 -> A=g_x, C=g_q ; 1 -> A=g_x, C=g_v ; 2 -> A=g_ao, C=g_pr
// 128x128 tile, BK=32, 256 threads, 8x8 per thread, packed FFMA2 inner loop,
// register double-buffered global loads.
__global__ void __launch_bounds__(256) gemm_bias_kernel(int sel,
                                                        const float* __restrict__ W,
                                                        const float* __restrict__ bias) {
    const float* A = (sel == 2) ? g_ao : g_x;
    float* C = (sel == 0) ? g_q : ((sel == 1) ? g_v : g_pr);

    __shared__ float As[32][128];
    __shared__ float Bs[32][128];

    int bx = blockIdx.x;           // N tile (8)
    int by = blockIdx.y;           // M tile (16)
    int tid = threadIdx.x;
    int tx = tid & 15, ty = tid >> 4;

    const float* Ab = A + (size_t)by * 128 * D_;
    const float* Wb = W + (size_t)bx * 128;

    // per-thread load coordinates (4 float4 each for A and B tiles)
    int agr[4], agk[4], bgr[4], bgc[4];
#pragma unroll
    for (int r = 0; r < 4; r++) {
        int g = tid + r * 256;      // 0..1023
        agr[r] = g >> 3;            // A row 0..127
        agk[r] = (g & 7) * 4;       // A k sub-offset 0..28
        bgr[r] = g >> 5;            // B row 0..31
        bgc[r] = (g & 31) * 4;      // B col
    }

    u64 acc[8][4];
#pragma unroll
    for (int i = 0; i < 8; i++)
#pragma unroll
        for (int j = 0; j < 4; j++) acc[i][j] = 0ull;

    float4 pa[4], pb[4];
    // preload k0 = 0
#pragma unroll
    for (int r = 0; r < 4; r++) {
        pa[r] = *(const float4*)(Ab + (size_t)agr[r] * D_ + agk[r]);
        pb[r] = *(const float4*)(Wb + (size_t)bgr[r] * D_ + bgc[r]);
    }
#pragma unroll
    for (int r = 0; r < 4; r++) {
        As[agk[r] + 0][agr[r]] = pa[r].x;
        As[agk[r] + 1][agr[r]] = pa[r].y;
        As[agk[r] + 2][agr[r]] = pa[r].z;
        As[agk[r] + 3][agr[r]] = pa[r].w;
        *(float4*)&Bs[bgr[r]][bgc[r]] = pb[r];
    }
    __syncthreads();

    for (int k0 = 0; k0 < D_; k0 += 32) {
        int kn = k0 + 32;
        if (kn < D_) {
            // issue next tile's global loads early (overlap with compute)
#pragma unroll
            for (int r = 0; r < 4; r++) {
                pa[r] = *(const float4*)(Ab + (size_t)agr[r] * D_ + kn + agk[r]);
                pb[r] = *(const float4*)(Wb + (size_t)(kn + bgr[r]) * D_ + bgc[r]);
            }
        }
#pragma unroll
        for (int k = 0; k < 32; k++) {
            float4 ra0 = *(const float4*)&As[k][ty * 8];
            float4 ra1 = *(const float4*)&As[k][ty * 8 + 4];
            const u64* rbp = (const u64*)&Bs[k][tx * 8];
            u64 rb[4] = {rbp[0], rbp[1], rbp[2], rbp[3]};
            float ra[8] = {ra0.x, ra0.y, ra0.z, ra0.w, ra1.x, ra1.y, ra1.z, ra1.w};
#pragma unroll
            for (int i = 0; i < 8; i++) {
                u64 ad = pack2(ra[i], ra[i]);
#pragma unroll
                for (int j = 0; j < 4; j++) fma2(acc[i][j], ad, rb[j]);
            }
        }
        __syncthreads();
        if (kn < D_) {
#pragma unroll
            for (int r = 0; r < 4; r++) {
                As[agk[r] + 0][agr[r]] = pa[r].x;
                As[agk[r] + 1][agr[r]] = pa[r].y;
                As[agk[r] + 2][agr[r]] = pa[r].z;
                As[agk[r] + 3][agr[r]] = pa[r].w;
                *(float4*)&Bs[bgr[r]][bgc[r]] = pb[r];
            }
            __syncthreads();
        }
    }

#pragma unroll
    for (int i = 0; i < 8; i++) {
        int row = by * 128 + ty * 8 + i;
#pragma unroll
        for (int j = 0; j < 2; j++) {
            int col = bx * 128 + tx * 8 + j * 4;
            float a0, a1, a2, a3;
            unpack2(acc[i][j * 2 + 0], a0, a1);
            unpack2(acc[i][j * 2 + 1], a2, a3);
            float4 v;
            v.x = a0 + bias[col + 0];
            v.y = a1 + bias[col + 1];
            v.z = a2 + bias[col + 2];
            v.w = a3 + bias[col + 3];
            *(float4*)(C + (size_t)row * D_ + col) = v;
        }
    }
}

// ---------------- scores: g_sc[bh][i][j] = dot(Qh_i, Qh_j)/8, lower tiles only ----
// 128x128 tile, 8x8 per thread, k=64 streamed as two 32-deep smem chunks.
__global__ void __launch_bounds__(256) scores_kernel() {
    int jt = blockIdx.x;   // key tile (128 wide)
    int it = blockIdx.y;   // query tile (128 wide)
    int bh = blockIdx.z;
    if (jt > it) return;   // strictly-causal: only j <= i tiles needed

    int b = bh / H_, h = bh % H_;
    const float* Qb = g_q + (size_t)b * S_ * D_ + h * DH_;

    __shared__ float As[32][128];  // [k][i]
    __shared__ float Bs[32][128];  // [k][j]

    int tid = threadIdx.x;
    int tx = tid & 15, ty = tid >> 4;

    int lr[4], lk[4];
#pragma unroll
    for (int r = 0; r < 4; r++) {
        int g = tid + r * 256;   // 0..1023
        lr[r] = g >> 3;          // row 0..127
        lk[r] = (g & 7) * 4;     // k sub-offset 0..28
    }

    u64 acc[8][4];
#pragma unroll
    for (int i = 0; i < 8; i++)
#pragma unroll
        for (int j = 0; j < 4; j++) acc[i][j] = 0ull;

    float4 pa[4], pb[4];
    // preload chunk 0 (k = 0..31)
#pragma unroll
    for (int r = 0; r < 4; r++) {
        pa[r] = *(const float4*)(Qb + (size_t)(it * 128 + lr[r]) * D_ + lk[r]);
        pb[r] = *(const float4*)(Qb + (size_t)(jt * 128 + lr[r]) * D_ + lk[r]);
    }
#pragma unroll
    for (int r = 0; r < 4; r++) {
        As[lk[r] + 0][lr[r]] = pa[r].x; As[lk[r] + 1][lr[r]] = pa[r].y;
        As[lk[r] + 2][lr[r]] = pa[r].z; As[lk[r] + 3][lr[r]] = pa[r].w;
        Bs[lk[r] + 0][lr[r]] = pb[r].x; Bs[lk[r] + 1][lr[r]] = pb[r].y;
        Bs[lk[r] + 2][lr[r]] = pb[r].z; Bs[lk[r] + 3][lr[r]] = pb[r].w;
    }
    __syncthreads();

#pragma unroll
    for (int c = 0; c < 2; c++) {
        if (c == 0) {
            // prefetch chunk 1 (k = 32..63)
#pragma unroll
            for (int r = 0; r < 4; r++) {
                pa[r] = *(const float4*)(Qb + (size_t)(it * 128 + lr[r]) * D_ + 32 + lk[r]);
                pb[r] = *(const float4*)(Qb + (size_t)(jt * 128 + lr[r]) * D_ + 32 + lk[r]);
            }
        }
#pragma unroll
        for (int k = 0; k < 32; k++) {
            float4 ra0 = *(const float4*)&As[k][ty * 8];
            float4 ra1 = *(const float4*)&As[k][ty * 8 + 4];
            const u64* rbp = (const u64*)&Bs[k][tx * 8];
            u64 rb[4] = {rbp[0], rbp[1], rbp[2], rbp[3]};
            float ra[8] = {ra0.x, ra0.y, ra0.z, ra0.w, ra1.x, ra1.y, ra1.z, ra1.w};
#pragma unroll
            for (int i = 0; i < 8; i++) {
                u64 ad = pack2(ra[i], ra[i]);
#pragma unroll
                for (int j = 0; j < 4; j++) fma2(acc[i][j], ad, rb[j]);
            }
        }
        __syncthreads();
        if (c == 0) {
#pragma unroll
            for (int r = 0; r < 4; r++) {
                As[lk[r] + 0][lr[r]] = pa[r].x; As[lk[r] + 1][lr[r]] = pa[r].y;
                As[lk[r] + 2][lr[r]] = pa[r].z; As[lk[r] + 3][lr[r]] = pa[r].w;
                Bs[lk[r] + 0][lr[r]] = pb[r].x; Bs[lk[r] + 1][lr[r]] = pb[r].y;
                Bs[lk[r] + 2][lr[r]] = pb[r].z; Bs[lk[r] + 3][lr[r]] = pb[r].w;
            }
            __syncthreads();
        }
    }

    float* out = g_sc + (size_t)bh * S_ * S_;
#pragma unroll
    for (int i = 0; i < 8; i++) {
        int row = it * 128 + ty * 8 + i;
#pragma unroll
        for (int j = 0; j < 2; j++) {
            int col = jt * 128 + tx * 8 + j * 4;
            float a0, a1, a2, a3;
            unpack2(acc[i][j * 2 + 0], a0, a1);
            unpack2(acc[i][j * 2 + 1], a2, a3);
            float4 v = {a0 * 0.125f, a1 * 0.125f, a2 * 0.125f, a3 * 0.125f};
            *(float4*)(out + (size_t)row * S_ + col) = v;
        }
    }
}

// ---------------- per-row gamma-attention pipeline (warp per row) ----------------
// Each warp owns one (bh, q) row of 1024 scores. Thread owns contiguous 32-elem
// chunk (one 128B line). All reductions are shuffles; no __syncthreads.
__global__ void __launch_bounds__(256) row_kernel(const float* __restrict__ gammas, int layer) {
    int warp = threadIdx.x >> 5, lane = threadIdx.x & 31;
    int q = blockIdx.x * 8 + warp;     // 0..1023
    int bh = blockIdx.y;
    int h = bh % H_;
    float* rowp = g_sc + (size_t)bh * S_ * S_ + (size_t)q * S_;
    float* chunk = rowp + lane * 32;

    if (q == 0) {                      // fully-masked row -> attn = 0
        float4 z = {0.f, 0.f, 0.f, 0.f};
#pragma unroll
        for (int i = 0; i < 8; i++) *(float4*)(chunk + i * 4) = z;
        return;
    }

    int kbase = lane * 32;
    float s[32];
#pragma unroll
    for (int i = 0; i < 8; i++) {
        float4 v = *(const float4*)(chunk + i * 4);
        s[i * 4 + 0] = v.x; s[i * 4 + 1] = v.y; s[i * 4 + 2] = v.z; s[i * 4 + 3] = v.w;
    }

    // ---- first masked softmax (unnormalized e, denom) ----
    float lmax = -INFINITY;
#pragma unroll
    for (int i = 0; i < 32; i++)
        if (kbase + i < q) lmax = fmaxf(lmax, s[i]);
    float m1 = warp_max(lmax);

    float e[32];
    float lsum = 0.f;
#pragma unroll
    for (int i = 0; i < 32; i++) {
        e[i] = (kbase + i < q) ? expf(s[i] - m1) : 0.f;
        lsum += e[i];
    }
    float denom = warp_sum(lsum);
    float inv_denom = 1.0f / denom;

    // ---- inclusive cumsum of e across the row (local scan + warp offset) ----
    float incl = warp_iscan(lsum, lane);
    float excl = incl - lsum;
    float tot_e = __shfl_sync(0xffffffffu, incl, 31);
    float total = tot_e * inv_denom;   // == sum(p)

    // ---- distance decay + second softmax input ----
    float g = -fabsf(gammas[layer * H_ + h]);
    float run = excl;
    float lmax2 = -INFINITY;
#pragma unroll
    for (int i = 0; i < 32; i++) {
        run += e[i];
        int k = kbase + i;
        float cum = run * inv_denom;                   // cumsum(p) inclusive
        float dd = fabsf((float)(q - k));
        float dist = sqrtf(fmaxf((total - cum) * dd, 0.f));
        float eff = expf(dist * g);
        eff = fminf(fmaxf(eff, 1e-5f), 1e5f);
        float s2 = (k < q) ? s[i] * eff : -INFINITY;
        s[i] = s2;
        lmax2 = fmaxf(lmax2, s2);
    }
    float m2 = warp_max(lmax2);

    float lsum2 = 0.f;
#pragma unroll
    for (int i = 0; i < 32; i++) {
        e[i] = (kbase + i < q) ? expf(s[i] - m2) : 0.f;
        lsum2 += e[i];
    }
    float d2 = warp_sum(lsum2);
    float inv_d2 = 1.0f / d2;

    // ---- maxout rescale: a = e/d2; scale = min(1/max(a), 5) ----
    float lamax = 0.f;
#pragma unroll
    for (int i = 0; i < 32; i++) lamax = fmaxf(lamax, e[i]);
    float amax = warp_max(lamax) * inv_d2;
    float scale = fminf(1.0f / amax, 5.0f) * inv_d2;

#pragma unroll
    for (int i = 0; i < 8; i++) {
        float4 v;
        v.x = e[i * 4 + 0] * scale;
        v.y = e[i * 4 + 1] * scale;
        v.z = e[i * 4 + 2] * scale;
        v.w = e[i * 4 + 3] * scale;
        *(float4*)(chunk + i * 4) = v;
    }
}

// ---------------- PV: g_ao[b, i, h*64+d] = sum_k attn[bh][i][k] * Vh[k][d] --------
// Register double-buffered over kt tiles.
__global__ void __launch_bounds__(256) pv_kernel() {
    int it = blockIdx.x;   // query row tile (16)
    int bh = blockIdx.y;
    int b = bh / H_, h = bh % H_;
    const float* att = g_sc + (size_t)bh * S_ * S_;
    const float* Vb = g_v + (size_t)b * S_ * D_ + h * DH_;
    float* Ob = g_ao + (size_t)b * S_ * D_ + h * DH_;

    __shared__ float As[64][64];  // attn transposed: [k][i]
    __shared__ float Bs[64][64];  // V: [k][d]

    int tid = threadIdx.x, tx = tid & 15, ty = tid >> 4;

    // load coordinates: 4 float4 per tile per array
    int lrow[4], lcq[4];
#pragma unroll
    for (int r = 0; r < 4; r++) {
        int g = tid + r * 256;
        lrow[r] = g >> 4;      // 0..63
        lcq[r] = (g & 15) * 4; // col offset
    }

    u64 acc[4][2];
#pragma unroll
    for (int i = 0; i < 4; i++) { acc[i][0] = 0ull; acc[i][1] = 0ull; }

    float4 va[4], vb[4];
    // preload kt = 0
#pragma unroll
    for (int r = 0; r < 4; r++) {
        va[r] = *(const float4*)(att + (size_t)(it * 64 + lrow[r]) * S_ + lcq[r]);
        vb[r] = *(const float4*)(Vb + (size_t)lrow[r] * D_ + lcq[r]);
    }
#pragma unroll
    for (int r = 0; r < 4; r++) {
        As[lcq[r] + 0][lrow[r]] = va[r].x; As[lcq[r] + 1][lrow[r]] = va[r].y;
        As[lcq[r] + 2][lrow[r]] = va[r].z; As[lcq[r] + 3][lrow[r]] = va[r].w;
        *(float4*)&Bs[lrow[r]][lcq[r]] = vb[r];
    }
    __syncthreads();

    // causal: attn[i][k]==0 for k > i, so only chunks kt <= it contribute
    for (int kt = 0; kt <= it; kt++) {
        if (kt + 1 <= it) {
#pragma unroll
            for (int r = 0; r < 4; r++) {
                va[r] = *(const float4*)(att + (size_t)(it * 64 + lrow[r]) * S_ + (kt + 1) * 64 + lcq[r]);
                vb[r] = *(const float4*)(Vb + (size_t)((kt + 1) * 64 + lrow[r]) * D_ + lcq[r]);
            }
        }
#pragma unroll 8
        for (int k = 0; k < 64; k++) {
            float4 ra = *(const float4*)&As[k][ty * 4];
            const u64* rbp = (const u64*)&Bs[k][tx * 4];
            u64 rb0 = rbp[0], rb1 = rbp[1];
            float rav[4] = {ra.x, ra.y, ra.z, ra.w};
#pragma unroll
            for (int i = 0; i < 4; i++) {
                u64 ad = pack2(rav[i], rav[i]);
                fma2(acc[i][0], ad, rb0);
                fma2(acc[i][1], ad, rb1);
            }
        }
        __syncthreads();
        if (kt + 1 <= it) {
#pragma unroll
            for (int r = 0; r < 4; r++) {
                As[lcq[r] + 0][lrow[r]] = va[r].x; As[lcq[r] + 1][lrow[r]] = va[r].y;
                As[lcq[r] + 2][lrow[r]] = va[r].z; As[lcq[r] + 3][lrow[r]] = va[r].w;
                *(float4*)&Bs[lrow[r]][lcq[r]] = vb[r];
            }
            __syncthreads();
        }
    }

#pragma unroll
    for (int i = 0; i < 4; i++) {
        float a0, a1, a2, a3;
        unpack2(acc[i][0], a0, a1);
        unpack2(acc[i][1], a2, a3);
        float4 v = {a0, a1, a2, a3};
        *(float4*)(Ob + (size_t)(it * 64 + ty * 4 + i) * D_ + tx * 4) = v;
    }
}

// ---------------- (x [+ g_pr]) -> LayerNorm -> (g_x | out) ----------------
// addA=1: v = g_x + g_pr, write g_x.  addA=0: v = g_x, write `out`.
__global__ void __launch_bounds__(256) ln_kernel(const float* __restrict__ gw,
                                                 const float* __restrict__ bw,
                                                 float* __restrict__ out, int addA) {
    int row = blockIdx.x;
    int t = threadIdx.x;
    int lane = t & 31, wid = t >> 5;
    __shared__ float red[33];

    float4 xv = *(const float4*)(g_x + (size_t)row * D_ + t * 4);
    float v0 = xv.x, v1 = xv.y, v2 = xv.z, v3 = xv.w;
    if (addA) {
        float4 av = *(const float4*)(g_pr + (size_t)row * D_ + t * 4);
        v0 += av.x; v1 += av.y; v2 += av.z; v3 += av.w;
    }
    float ssum = warp_sum(v0 + v1 + v2 + v3);
    if (lane == 0) red[wid] = ssum;
    __syncthreads();
    if (wid == 0) {
        float u = (lane < 8) ? red[lane] : 0.0f;
        u = warp_sum(u);
        if (lane == 0) red[32] = u;
    }
    __syncthreads();
    float mu = red[32] * (1.0f / D_);
    __syncthreads();

    float d0 = v0 - mu, d1 = v1 - mu, d2 = v2 - mu, d3 = v3 - mu;
    float vs = warp_sum(d0 * d0 + d1 * d1 + d2 * d2 + d3 * d3);
    if (lane == 0) red[wid] = vs;
    __syncthreads();
    if (wid == 0) {
        float u = (lane < 8) ? red[lane] : 0.0f;
        u = warp_sum(u);
        if (lane == 0) red[32] = u;
    }
    __syncthreads();
    float var = red[32] * (1.0f / D_);
    float rs = rsqrtf(var + 1e-5f);

    float4 g4 = *(const float4*)(gw + t * 4);
    float4 b4 = *(const float4*)(bw + t * 4);
    float4 o;
    o.x = d0 * rs * g4.x + b4.x;
    o.y = d1 * rs * g4.y + b4.y;
    o.z = d2 * rs * g4.z + b4.z;
    o.w = d3 * rs * g4.w + b4.w;
    float* dst = addA ? g_x : out;
    *(float4*)(dst + (size_t)row * D_ + t * 4) = o;
}

// ---------------- launch ----------------
extern "C" void kernel_launch(void* const* d_in, const int* in_sizes, int n_in,
                              void* d_out, int out_size) {
    (void)in_sizes; (void)n_in; (void)out_size;
    const float* q      = (const float*)d_in[0];
    // d_in[1] = lens (unused in eval mode)
    const float* Wq     = (const float*)d_in[2];
    const float* bq     = (const float*)d_in[3];
    const float* Wv     = (const float*)d_in[4];
    const float* bv     = (const float*)d_in[5];
    const float* Wo     = (const float*)d_in[6];
    const float* bo     = (const float*)d_in[7];
    const float* gammas = (const float*)d_in[8];
    const float* ln_g   = (const float*)d_in[9];
    const float* ln_b   = (const float*)d_in[10];
    const float* fin_g  = (const float*)d_in[11];
    const float* fin_b  = (const float*)d_in[12];

    // x = q
    copy_in_kernel<<<(M_ * D_ / 4) / 256, 256>>>((const float4*)q);

    dim3 gemm_grid(D_ / 128, M_ / 128);     // (8, 16)
    for (int l = 0; l < L_; l++) {
        size_t wOff = (size_t)l * D_ * D_;
        gemm_bias_kernel<<<gemm_grid, 256>>>(0, Wq + wOff, bq + (size_t)l * D_);
        gemm_bias_kernel<<<gemm_grid, 256>>>(1, Wv + wOff, bv + (size_t)l * D_);
        scores_kernel<<<dim3(S_ / 128, S_ / 128, BH_), 256>>>();
        row_kernel<<<dim3(S_ / 8, BH_), 256>>>(gammas, l);
        pv_kernel<<<dim3(S_ / 64, BH_), 256>>>();
        gemm_bias_kernel<<<gemm_grid, 256>>>(2, Wo + wOff, bo + (size_t)l * D_);
        ln_kernel<<<M_, 256>>>(ln_g + (size_t)l * D_, ln_b + (size_t)l * D_, nullptr, 1);
    }
    // final layer norm -> output
    ln_kernel<<<M_, 256>>>(fin_g, fin_b, (float*)d_out, 0);
}

// round 10
// speedup vs baseline: 1.0448x; 1.0132x over previous
#include <cuda_runtime.h>
#include <cmath>

// Problem constants
#define B_ 2
#define S_ 1024
#define D_ 1024
#define H_ 16
#define L_ 4
#define DH_ 64
#define BH_ (B_ * H_)
#define M_ (B_ * S_)   // 2048 rows

typedef unsigned long long u64;

// ---------------- scratch (device globals; allocation-free) ----------------
__device__ __align__(16) float g_x [(size_t)B_ * S_ * D_];   // current residual stream x
__device__ __align__(16) float g_q [(size_t)B_ * S_ * D_];   // Q (=K) projection
__device__ __align__(16) float g_v [(size_t)B_ * S_ * D_];   // V projection
__device__ __align__(16) float g_ao[(size_t)B_ * S_ * D_];   // attn output pre-Wo
__device__ __align__(16) float g_pr[(size_t)B_ * S_ * D_];   // Wo projection output
__device__ __align__(16) float g_sc[(size_t)B_ * H_ * S_ * S_]; // scores/attn scratch (134MB)

// ---------------- packed f32x2 helpers (sm_100+) ----------------
__device__ __forceinline__ void fma2(u64& d, u64 a, u64 b) {
    asm("fma.rn.f32x2 %0, %1, %2, %0;" : "+l"(d) : "l"(a), "l"(b));
}
__device__ __forceinline__ u64 pack2(float lo, float hi) {
    u64 r;
    asm("mov.b64 %0, {%1, %2};" : "=l"(r) : "f"(lo), "f"(hi));
    return r;
}
__device__ __forceinline__ void unpack2(u64 v, float& lo, float& hi) {
    asm("mov.b64 {%0, %1}, %2;" : "=f"(lo), "=f"(hi) : "l"(v));
}

// ---------------- warp reduction helpers ----------------
__device__ __forceinline__ float warp_max(float v) {
#pragma unroll
    for (int o = 16; o > 0; o >>= 1) v = fmaxf(v, __shfl_xor_sync(0xffffffffu, v, o));
    return v;
}
__device__ __forceinline__ float warp_sum(float v) {
#pragma unroll
    for (int o = 16; o > 0; o >>= 1) v += __shfl_xor_sync(0xffffffffu, v, o);
    return v;
}
__device__ __forceinline__ float warp_iscan(float v, int lane) {
#pragma unroll
    for (int o = 1; o < 32; o <<= 1) {
        float u = __shfl_up_sync(0xffffffffu, v, o);
        if (lane >= o) v += u;
    }
    return v;
}

// ---------------- input copy: q -> g_x ----------------
__global__ void copy_in_kernel(const float4* __restrict__ src) {
    size_t i = (size_t)blockIdx.x * 256 + threadIdx.x;
    reinterpret_cast<float4*>(g_x)[i] = src[i];
}

// ---------------- projection GEMM core --------------------------------------
// C = A(2048x1024) @ W(1024x1024) + bias. 128x128 tile, BK=32, 256 threads,
// 8x8 per thread, packed FFMA2, register double-buffered loads, 2 CTAs/SM.
__device__ __forceinline__ void gemm_core(const float* __restrict__ A,
                                          const float* __restrict__ W,
                                          const float* __restrict__ bias,
                                          float* __restrict__ C,
                                          int bx, int by) {
    __shared__ float As[32][128];
    __shared__ float Bs[32][128];

    int tid = threadIdx.x;
    int tx = tid & 15, ty = tid >> 4;

    const float* Ab = A + (size_t)by * 128 * D_;
    const float* Wb = W + (size_t)bx * 128;

    u64 acc[8][4];
#pragma unroll
    for (int i = 0; i < 8; i++)
#pragma unroll
        for (int j = 0; j < 4; j++) acc[i][j] = 0ull;

    float4 pa[4], pb[4];
    // preload k0 = 0
#pragma unroll
    for (int r = 0; r < 4; r++) {
        int g = tid + r * 256;
        pa[r] = *(const float4*)(Ab + (size_t)(g >> 3) * D_ + (g & 7) * 4);
        pb[r] = *(const float4*)(Wb + (size_t)(g >> 5) * D_ + (g & 31) * 4);
    }
#pragma unroll
    for (int r = 0; r < 4; r++) {
        int g = tid + r * 256;
        int ar = g >> 3, ak = (g & 7) * 4;
        As[ak + 0][ar] = pa[r].x; As[ak + 1][ar] = pa[r].y;
        As[ak + 2][ar] = pa[r].z; As[ak + 3][ar] = pa[r].w;
        *(float4*)&Bs[g >> 5][(g & 31) * 4] = pb[r];
    }
    __syncthreads();

    for (int k0 = 0; k0 < D_; k0 += 32) {
        int kn = k0 + 32;
        if (kn < D_) {
#pragma unroll
            for (int r = 0; r < 4; r++) {
                int g = tid + r * 256;
                pa[r] = *(const float4*)(Ab + (size_t)(g >> 3) * D_ + kn + (g & 7) * 4);
                pb[r] = *(const float4*)(Wb + (size_t)(kn + (g >> 5)) * D_ + (g & 31) * 4);
            }
        }
#pragma unroll
        for (int k = 0; k < 32; k++) {
            float4 ra0 = *(const float4*)&As[k][ty * 8];
            float4 ra1 = *(const float4*)&As[k][ty * 8 + 4];
            const u64* rbp = (const u64*)&Bs[k][tx * 8];
            u64 rb[4] = {rbp[0], rbp[1], rbp[2], rbp[3]};
            float ra[8] = {ra0.x, ra0.y, ra0.z, ra0.w, ra1.x, ra1.y, ra1.z, ra1.w};
#pragma unroll
            for (int i = 0; i < 8; i++) {
                u64 ad = pack2(ra[i], ra[i]);
#pragma unroll
                for (int j = 0; j < 4; j++) fma2(acc[i][j], ad, rb[j]);
            }
        }
        __syncthreads();
        if (kn < D_) {
#pragma unroll
            for (int r = 0; r < 4; r++) {
                int g = tid + r * 256;
                int ar = g >> 3, ak = (g & 7) * 4;
                As[ak + 0][ar] = pa[r].x; As[ak + 1][ar] = pa[r].y;
                As[ak + 2][ar] = pa[r].z; As[ak + 3][ar] = pa[r].w;
                *(float4*)&Bs[g >> 5][(g & 31) * 4] = pb[r];
            }
            __syncthreads();
        }
    }

#pragma unroll
    for (int i = 0; i < 8; i++) {
        int row = by * 128 + ty * 8 + i;
#pragma unroll
        for (int j = 0; j < 2; j++) {
            int col = bx * 128 + tx * 8 + j * 4;
            float a0, a1, a2, a3;
            unpack2(acc[i][j * 2 + 0], a0, a1);
            unpack2(acc[i][j * 2 + 1], a2, a3);
            float4 v;
            v.x = a0 + bias[col + 0];
            v.y = a1 + bias[col + 1];
            v.z = a2 + bias[col + 2];
            v.w = a3 + bias[col + 3];
            *(float4*)(C + (size_t)row * D_ + col) = v;
        }
    }
}

// Q and V projections fused in one launch: z=0 -> Wq->g_q, z=1 -> Wv->g_v
__global__ void __launch_bounds__(256, 2) gemm_qv_kernel(const float* __restrict__ Wq,
                                                         const float* __restrict__ bq,
                                                         const float* __restrict__ Wv,
                                                         const float* __restrict__ bv) {
    if (blockIdx.z == 0)
        gemm_core(g_x, Wq, bq, g_q, blockIdx.x, blockIdx.y);
    else
        gemm_core(g_x, Wv, bv, g_v, blockIdx.x, blockIdx.y);
}

// Wo projection: g_ao @ Wo + bo -> g_pr
__global__ void __launch_bounds__(256, 2) gemm_o_kernel(const float* __restrict__ Wo,
                                                        const float* __restrict__ bo) {
    gemm_core(g_ao, Wo, bo, g_pr, blockIdx.x, blockIdx.y);
}

// ---------------- scores: g_sc[bh][i][j] = dot(Qh_i, Qh_j)/8, lower tiles only ----
// 128x128 tile, 8x8 per thread, k=64 streamed as two 32-deep smem chunks.
__global__ void __launch_bounds__(256, 2) scores_kernel() {
    int jt = blockIdx.x;   // key tile (128 wide)
    int it = blockIdx.y;   // query tile (128 wide)
    int bh = blockIdx.z;
    if (jt > it) return;   // strictly-causal: only j <= i tiles needed

    int b = bh / H_, h = bh % H_;
    const float* Qb = g_q + (size_t)b * S_ * D_ + h * DH_;

    __shared__ float As[32][128];  // [k][i]
    __shared__ float Bs[32][128];  // [k][j]

    int tid = threadIdx.x;
    int tx = tid & 15, ty = tid >> 4;

    u64 acc[8][4];
#pragma unroll
    for (int i = 0; i < 8; i++)
#pragma unroll
        for (int j = 0; j < 4; j++) acc[i][j] = 0ull;

    float4 pa[4], pb[4];
    // preload chunk 0 (k = 0..31)
#pragma unroll
    for (int r = 0; r < 4; r++) {
        int g = tid + r * 256;
        pa[r] = *(const float4*)(Qb + (size_t)(it * 128 + (g >> 3)) * D_ + (g & 7) * 4);
        pb[r] = *(const float4*)(Qb + (size_t)(jt * 128 + (g >> 3)) * D_ + (g & 7) * 4);
    }
#pragma unroll
    for (int r = 0; r < 4; r++) {
        int g = tid + r * 256;
        int lr = g >> 3, lk = (g & 7) * 4;
        As[lk + 0][lr] = pa[r].x; As[lk + 1][lr] = pa[r].y;
        As[lk + 2][lr] = pa[r].z; As[lk + 3][lr] = pa[r].w;
        Bs[lk + 0][lr] = pb[r].x; Bs[lk + 1][lr] = pb[r].y;
        Bs[lk + 2][lr] = pb[r].z; Bs[lk + 3][lr] = pb[r].w;
    }
    __syncthreads();

#pragma unroll
    for (int c = 0; c < 2; c++) {
        if (c == 0) {
            // prefetch chunk 1 (k = 32..63)
#pragma unroll
            for (int r = 0; r < 4; r++) {
                int g = tid + r * 256;
                pa[r] = *(const float4*)(Qb + (size_t)(it * 128 + (g >> 3)) * D_ + 32 + (g & 7) * 4);
                pb[r] = *(const float4*)(Qb + (size_t)(jt * 128 + (g >> 3)) * D_ + 32 + (g & 7) * 4);
            }
        }
#pragma unroll
        for (int k = 0; k < 32; k++) {
            float4 ra0 = *(const float4*)&As[k][ty * 8];
            float4 ra1 = *(const float4*)&As[k][ty * 8 + 4];
            const u64* rbp = (const u64*)&Bs[k][tx * 8];
            u64 rb[4] = {rbp[0], rbp[1], rbp[2], rbp[3]};
            float ra[8] = {ra0.x, ra0.y, ra0.z, ra0.w, ra1.x, ra1.y, ra1.z, ra1.w};
#pragma unroll
            for (int i = 0; i < 8; i++) {
                u64 ad = pack2(ra[i], ra[i]);
#pragma unroll
                for (int j = 0; j < 4; j++) fma2(acc[i][j], ad, rb[j]);
            }
        }
        __syncthreads();
        if (c == 0) {
#pragma unroll
            for (int r = 0; r < 4; r++) {
                int g = tid + r * 256;
                int lr = g >> 3, lk = (g & 7) * 4;
                As[lk + 0][lr] = pa[r].x; As[lk + 1][lr] = pa[r].y;
                As[lk + 2][lr] = pa[r].z; As[lk + 3][lr] = pa[r].w;
                Bs[lk + 0][lr] = pb[r].x; Bs[lk + 1][lr] = pb[r].y;
                Bs[lk + 2][lr] = pb[r].z; Bs[lk + 3][lr] = pb[r].w;
            }
            __syncthreads();
        }
    }

    float* out = g_sc + (size_t)bh * S_ * S_;
#pragma unroll
    for (int i = 0; i < 8; i++) {
        int row = it * 128 + ty * 8 + i;
#pragma unroll
        for (int j = 0; j < 2; j++) {
            int col = jt * 128 + tx * 8 + j * 4;
            float a0, a1, a2, a3;
            unpack2(acc[i][j * 2 + 0], a0, a1);
            unpack2(acc[i][j * 2 + 1], a2, a3);
            float4 v = {a0 * 0.125f, a1 * 0.125f, a2 * 0.125f, a3 * 0.125f};
            *(float4*)(out + (size_t)row * S_ + col) = v;
        }
    }
}

// ---------------- per-row gamma-attention pipeline (warp per row) ----------------
// Each warp owns one (bh, q) row of 1024 scores. Thread owns contiguous 32-elem
// chunk (one 128B line). All reductions are shuffles; no __syncthreads.
__global__ void __launch_bounds__(256) row_kernel(const float* __restrict__ gammas, int layer) {
    int warp = threadIdx.x >> 5, lane = threadIdx.x & 31;
    int q = blockIdx.x * 8 + warp;     // 0..1023
    int bh = blockIdx.y;
    int h = bh % H_;
    float* rowp = g_sc + (size_t)bh * S_ * S_ + (size_t)q * S_;
    float* chunk = rowp + lane * 32;

    if (q == 0) {                      // fully-masked row -> attn = 0
        float4 z = {0.f, 0.f, 0.f, 0.f};
#pragma unroll
        for (int i = 0; i < 8; i++) *(float4*)(chunk + i * 4) = z;
        return;
    }

    int kbase = lane * 32;
    float s[32];
#pragma unroll
    for (int i = 0; i < 8; i++) {
        float4 v = *(const float4*)(chunk + i * 4);
        s[i * 4 + 0] = v.x; s[i * 4 + 1] = v.y; s[i * 4 + 2] = v.z; s[i * 4 + 3] = v.w;
    }

    // ---- first masked softmax (unnormalized e, denom) ----
    float lmax = -INFINITY;
#pragma unroll
    for (int i = 0; i < 32; i++)
        if (kbase + i < q) lmax = fmaxf(lmax, s[i]);
    float m1 = warp_max(lmax);

    float e[32];
    float lsum = 0.f;
#pragma unroll
    for (int i = 0; i < 32; i++) {
        e[i] = (kbase + i < q) ? expf(s[i] - m1) : 0.f;
        lsum += e[i];
    }
    float denom = warp_sum(lsum);
    float inv_denom = 1.0f / denom;

    // ---- inclusive cumsum of e across the row (local scan + warp offset) ----
    float incl = warp_iscan(lsum, lane);
    float excl = incl - lsum;
    float tot_e = __shfl_sync(0xffffffffu, incl, 31);
    float total = tot_e * inv_denom;   // == sum(p)

    // ---- distance decay + second softmax input ----
    float g = -fabsf(gammas[layer * H_ + h]);
    float run = excl;
    float lmax2 = -INFINITY;
#pragma unroll
    for (int i = 0; i < 32; i++) {
        run += e[i];
        int k = kbase + i;
        float cum = run * inv_denom;                   // cumsum(p) inclusive
        float dd = fabsf((float)(q - k));
        float dist = sqrtf(fmaxf((total - cum) * dd, 0.f));
        float eff = expf(dist * g);
        eff = fminf(fmaxf(eff, 1e-5f), 1e5f);
        float s2 = (k < q) ? s[i] * eff : -INFINITY;
        s[i] = s2;
        lmax2 = fmaxf(lmax2, s2);
    }
    float m2 = warp_max(lmax2);

    float lsum2 = 0.f;
#pragma unroll
    for (int i = 0; i < 32; i++) {
        e[i] = (kbase + i < q) ? expf(s[i] - m2) : 0.f;
        lsum2 += e[i];
    }
    float d2 = warp_sum(lsum2);
    float inv_d2 = 1.0f / d2;

    // ---- maxout rescale: a = e/d2; scale = min(1/max(a), 5) ----
    float lamax = 0.f;
#pragma unroll
    for (int i = 0; i < 32; i++) lamax = fmaxf(lamax, e[i]);
    float amax = warp_max(lamax) * inv_d2;
    float scale = fminf(1.0f / amax, 5.0f) * inv_d2;

#pragma unroll
    for (int i = 0; i < 8; i++) {
        float4 v;
        v.x = e[i * 4 + 0] * scale;
        v.y = e[i * 4 + 1] * scale;
        v.z = e[i * 4 + 2] * scale;
        v.w = e[i * 4 + 3] * scale;
        *(float4*)(chunk + i * 4) = v;
    }
}

// ---------------- PV: g_ao[b, i, h*64+d] = sum_k attn[bh][i][k] * Vh[k][d] --------
// Register double-buffered over kt tiles.
__global__ void __launch_bounds__(256, 2) pv_kernel() {
    int it = blockIdx.x;   // query row tile (16)
    int bh = blockIdx.y;
    int b = bh / H_, h = bh % H_;
    const float* att = g_sc + (size_t)bh * S_ * S_;
    const float* Vb = g_v + (size_t)b * S_ * D_ + h * DH_;
    float* Ob = g_ao + (size_t)b * S_ * D_ + h * DH_;

    __shared__ float As[64][64];  // attn transposed: [k][i]
    __shared__ float Bs[64][64];  // V: [k][d]

    int tid = threadIdx.x, tx = tid & 15, ty = tid >> 4;

    // load coordinates: 4 float4 per tile per array
    int lrow[4], lcq[4];
#pragma unroll
    for (int r = 0; r < 4; r++) {
        int g = tid + r * 256;
        lrow[r] = g >> 4;      // 0..63
        lcq[r] = (g & 15) * 4; // col offset
    }

    u64 acc[4][2];
#pragma unroll
    for (int i = 0; i < 4; i++) { acc[i][0] = 0ull; acc[i][1] = 0ull; }

    float4 va[4], vb[4];
    // preload kt = 0
#pragma unroll
    for (int r = 0; r < 4; r++) {
        va[r] = *(const float4*)(att + (size_t)(it * 64 + lrow[r]) * S_ + lcq[r]);
        vb[r] = *(const float4*)(Vb + (size_t)lrow[r] * D_ + lcq[r]);
    }
#pragma unroll
    for (int r = 0; r < 4; r++) {
        As[lcq[r] + 0][lrow[r]] = va[r].x; As[lcq[r] + 1][lrow[r]] = va[r].y;
        As[lcq[r] + 2][lrow[r]] = va[r].z; As[lcq[r] + 3][lrow[r]] = va[r].w;
        *(float4*)&Bs[lrow[r]][lcq[r]] = vb[r];
    }
    __syncthreads();

    // causal: attn[i][k]==0 for k > i, so only chunks kt <= it contribute
    for (int kt = 0; kt <= it; kt++) {
        if (kt + 1 <= it) {
#pragma unroll
            for (int r = 0; r < 4; r++) {
                va[r] = *(const float4*)(att + (size_t)(it * 64 + lrow[r]) * S_ + (kt + 1) * 64 + lcq[r]);
                vb[r] = *(const float4*)(Vb + (size_t)((kt + 1) * 64 + lrow[r]) * D_ + lcq[r]);
            }
        }
#pragma unroll 8
        for (int k = 0; k < 64; k++) {
            float4 ra = *(const float4*)&As[k][ty * 4];
            const u64* rbp = (const u64*)&Bs[k][tx * 4];
            u64 rb0 = rbp[0], rb1 = rbp[1];
            float rav[4] = {ra.x, ra.y, ra.z, ra.w};
#pragma unroll
            for (int i = 0; i < 4; i++) {
                u64 ad = pack2(rav[i], rav[i]);
                fma2(acc[i][0], ad, rb0);
                fma2(acc[i][1], ad, rb1);
            }
        }
        __syncthreads();
        if (kt + 1 <= it) {
#pragma unroll
            for (int r = 0; r < 4; r++) {
                As[lcq[r] + 0][lrow[r]] = va[r].x; As[lcq[r] + 1][lrow[r]] = va[r].y;
                As[lcq[r] + 2][lrow[r]] = va[r].z; As[lcq[r] + 3][lrow[r]] = va[r].w;
                *(float4*)&Bs[lrow[r]][lcq[r]] = vb[r];
            }
            __syncthreads();
        }
    }

#pragma unroll
    for (int i = 0; i < 4; i++) {
        float a0, a1, a2, a3;
        unpack2(acc[i][0], a0, a1);
        unpack2(acc[i][1], a2, a3);
        float4 v = {a0, a1, a2, a3};
        *(float4*)(Ob + (size_t)(it * 64 + ty * 4 + i) * D_ + tx * 4) = v;
    }
}

// ---------------- (x [+ g_pr]) -> LayerNorm -> (g_x | out) ----------------
// addA=1: v = g_x + g_pr, write g_x.  addA=0: v = g_x, write `out`.
__global__ void __launch_bounds__(256) ln_kernel(const float* __restrict__ gw,
                                                 const float* __restrict__ bw,
                                                 float* __restrict__ out, int addA) {
    int row = blockIdx.x;
    int t = threadIdx.x;
    int lane = t & 31, wid = t >> 5;
    __shared__ float red[33];

    float4 xv = *(const float4*)(g_x + (size_t)row * D_ + t * 4);
    float v0 = xv.x, v1 = xv.y, v2 = xv.z, v3 = xv.w;
    if (addA) {
        float4 av = *(const float4*)(g_pr + (size_t)row * D_ + t * 4);
        v0 += av.x; v1 += av.y; v2 += av.z; v3 += av.w;
    }
    float ssum = warp_sum(v0 + v1 + v2 + v3);
    if (lane == 0) red[wid] = ssum;
    __syncthreads();
    if (wid == 0) {
        float u = (lane < 8) ? red[lane] : 0.0f;
        u = warp_sum(u);
        if (lane == 0) red[32] = u;
    }
    __syncthreads();
    float mu = red[32] * (1.0f / D_);
    __syncthreads();

    float d0 = v0 - mu, d1 = v1 - mu, d2 = v2 - mu, d3 = v3 - mu;
    float vs = warp_sum(d0 * d0 + d1 * d1 + d2 * d2 + d3 * d3);
    if (lane == 0) red[wid] = vs;
    __syncthreads();
    if (wid == 0) {
        float u = (lane < 8) ? red[lane] : 0.0f;
        u = warp_sum(u);
        if (lane == 0) red[32] = u;
    }
    __syncthreads();
    float var = red[32] * (1.0f / D_);
    float rs = rsqrtf(var + 1e-5f);

    float4 g4 = *(const float4*)(gw + t * 4);
    float4 b4 = *(const float4*)(bw + t * 4);
    float4 o;
    o.x = d0 * rs * g4.x + b4.x;
    o.y = d1 * rs * g4.y + b4.y;
    o.z = d2 * rs * g4.z + b4.z;
    o.w = d3 * rs * g4.w + b4.w;
    float* dst = addA ? g_x : out;
    *(float4*)(dst + (size_t)row * D_ + t * 4) = o;
}

// ---------------- launch ----------------
extern "C" void kernel_launch(void* const* d_in, const int* in_sizes, int n_in,
                              void* d_out, int out_size) {
    (void)in_sizes; (void)n_in; (void)out_size;
    const float* q      = (const float*)d_in[0];
    // d_in[1] = lens (unused in eval mode)
    const float* Wq     = (const float*)d_in[2];
    const float* bq     = (const float*)d_in[3];
    const float* Wv     = (const float*)d_in[4];
    const float* bv     = (const float*)d_in[5];
    const float* Wo     = (const float*)d_in[6];
    const float* bo     = (const float*)d_in[7];
    const float* gammas = (const float*)d_in[8];
    const float* ln_g   = (const float*)d_in[9];
    const float* ln_b   = (const float*)d_in[10];
    const float* fin_g  = (const float*)d_in[11];
    const float* fin_b  = (const float*)d_in[12];

    // x = q
    copy_in_kernel<<<(M_ * D_ / 4) / 256, 256>>>((const float4*)q);

    dim3 qv_grid(D_ / 128, M_ / 128, 2);    // (8, 16, 2)
    dim3 o_grid(D_ / 128, M_ / 128);        // (8, 16)
    for (int l = 0; l < L_; l++) {
        size_t wOff = (size_t)l * D_ * D_;
        gemm_qv_kernel<<<qv_grid, 256>>>(Wq + wOff, bq + (size_t)l * D_,
                                         Wv + wOff, bv + (size_t)l * D_);
        scores_kernel<<<dim3(S_ / 128, S_ / 128, BH_), 256>>>();
        row_kernel<<<dim3(S_ / 8, BH_), 256>>>(gammas, l);
        pv_kernel<<<dim3(S_ / 64, BH_), 256>>>();
        gemm_o_kernel<<<o_grid, 256>>>(Wo + wOff, bo + (size_t)l * D_);
        ln_kernel<<<M_, 256>>>(ln_g + (size_t)l * D_, ln_b + (size_t)l * D_, nullptr, 1);
    }
    // final layer norm -> output
    ln_kernel<<<M_, 256>>>(fin_g, fin_b, (float*)d_out, 0);
}

// round 11
// speedup vs baseline: 1.0962x; 1.0492x over previous
#include <cuda_runtime.h>
#include <cmath>

// Problem constants
#define B_ 2
#define S_ 1024
#define D_ 1024
#define H_ 16
#define L_ 4
#define DH_ 64
#define BH_ (B_ * H_)
#define M_ (B_ * S_)   // 2048 rows

typedef unsigned long long u64;

// ---------------- scratch (device globals; allocation-free) ----------------
__device__ __align__(16) float g_x [(size_t)B_ * S_ * D_];   // current residual stream x
__device__ __align__(16) float g_q [(size_t)B_ * S_ * D_];   // Q (=K) projection
__device__ __align__(16) float g_v [(size_t)B_ * S_ * D_];   // V projection
__device__ __align__(16) float g_ao[(size_t)B_ * S_ * D_];   // attn output pre-Wo
__device__ __align__(16) float g_pr[(size_t)B_ * S_ * D_];   // Wo projection output
__device__ __align__(16) float g_sc[(size_t)B_ * H_ * S_ * S_]; // scores/attn scratch (134MB)

// ---------------- packed f32x2 helpers (sm_100+) ----------------
__device__ __forceinline__ void fma2(u64& d, u64 a, u64 b) {
    asm("fma.rn.f32x2 %0, %1, %2, %0;" : "+l"(d) : "l"(a), "l"(b));
}
__device__ __forceinline__ u64 pack2(float lo, float hi) {
    u64 r;
    asm("mov.b64 %0, {%1, %2};" : "=l"(r) : "f"(lo), "f"(hi));
    return r;
}
__device__ __forceinline__ void unpack2(u64 v, float& lo, float& hi) {
    asm("mov.b64 {%0, %1}, %2;" : "=f"(lo), "=f"(hi) : "l"(v));
}
__device__ __forceinline__ float sqrt_approx(float x) {
    float r;
    asm("sqrt.approx.f32 %0, %1;" : "=f"(r) : "f"(x));
    return r;
}

// ---------------- warp reduction helpers ----------------
__device__ __forceinline__ float warp_max(float v) {
#pragma unroll
    for (int o = 16; o > 0; o >>= 1) v = fmaxf(v, __shfl_xor_sync(0xffffffffu, v, o));
    return v;
}
__device__ __forceinline__ float warp_sum(float v) {
#pragma unroll
    for (int o = 16; o > 0; o >>= 1) v += __shfl_xor_sync(0xffffffffu, v, o);
    return v;
}
__device__ __forceinline__ float warp_iscan(float v, int lane) {
#pragma unroll
    for (int o = 1; o < 32; o <<= 1) {
        float u = __shfl_up_sync(0xffffffffu, v, o);
        if (lane >= o) v += u;
    }
    return v;
}

// ---------------- input copy: q -> g_x ----------------
__global__ void copy_in_kernel(const float4* __restrict__ src) {
    size_t i = (size_t)blockIdx.x * 256 + threadIdx.x;
    reinterpret_cast<float4*>(g_x)[i] = src[i];
}

// ---------------- projection GEMM core --------------------------------------
// C = A(2048x1024) @ W(1024x1024) + bias. 128x128 tile, BK=32, 256 threads,
// 8x8 per thread, packed FFMA2, register double-buffered loads, 2 CTAs/SM.
__device__ __forceinline__ void gemm_core(const float* __restrict__ A,
                                          const float* __restrict__ W,
                                          const float* __restrict__ bias,
                                          float* __restrict__ C,
                                          int bx, int by) {
    __shared__ float As[32][128];
    __shared__ float Bs[32][128];

    int tid = threadIdx.x;
    int tx = tid & 15, ty = tid >> 4;

    const float* Ab = A + (size_t)by * 128 * D_;
    const float* Wb = W + (size_t)bx * 128;

    u64 acc[8][4];
#pragma unroll
    for (int i = 0; i < 8; i++)
#pragma unroll
        for (int j = 0; j < 4; j++) acc[i][j] = 0ull;

    float4 pa[4], pb[4];
    // preload k0 = 0
#pragma unroll
    for (int r = 0; r < 4; r++) {
        int g = tid + r * 256;
        pa[r] = *(const float4*)(Ab + (size_t)(g >> 3) * D_ + (g & 7) * 4);
        pb[r] = *(const float4*)(Wb + (size_t)(g >> 5) * D_ + (g & 31) * 4);
    }
#pragma unroll
    for (int r = 0; r < 4; r++) {
        int g = tid + r * 256;
        int ar = g >> 3, ak = (g & 7) * 4;
        As[ak + 0][ar] = pa[r].x; As[ak + 1][ar] = pa[r].y;
        As[ak + 2][ar] = pa[r].z; As[ak + 3][ar] = pa[r].w;
        *(float4*)&Bs[g >> 5][(g & 31) * 4] = pb[r];
    }
    __syncthreads();

    for (int k0 = 0; k0 < D_; k0 += 32) {
        int kn = k0 + 32;
        if (kn < D_) {
#pragma unroll
            for (int r = 0; r < 4; r++) {
                int g = tid + r * 256;
                pa[r] = *(const float4*)(Ab + (size_t)(g >> 3) * D_ + kn + (g & 7) * 4);
                pb[r] = *(const float4*)(Wb + (size_t)(kn + (g >> 5)) * D_ + (g & 31) * 4);
            }
        }
#pragma unroll
        for (int k = 0; k < 32; k++) {
            float4 ra0 = *(const float4*)&As[k][ty * 8];
            float4 ra1 = *(const float4*)&As[k][ty * 8 + 4];
            const u64* rbp = (const u64*)&Bs[k][tx * 8];
            u64 rb[4] = {rbp[0], rbp[1], rbp[2], rbp[3]};
            float ra[8] = {ra0.x, ra0.y, ra0.z, ra0.w, ra1.x, ra1.y, ra1.z, ra1.w};
#pragma unroll
            for (int i = 0; i < 8; i++) {
                u64 ad = pack2(ra[i], ra[i]);
#pragma unroll
                for (int j = 0; j < 4; j++) fma2(acc[i][j], ad, rb[j]);
            }
        }
        __syncthreads();
        if (kn < D_) {
#pragma unroll
            for (int r = 0; r < 4; r++) {
                int g = tid + r * 256;
                int ar = g >> 3, ak = (g & 7) * 4;
                As[ak + 0][ar] = pa[r].x; As[ak + 1][ar] = pa[r].y;
                As[ak + 2][ar] = pa[r].z; As[ak + 3][ar] = pa[r].w;
                *(float4*)&Bs[g >> 5][(g & 31) * 4] = pb[r];
            }
            __syncthreads();
        }
    }

#pragma unroll
    for (int i = 0; i < 8; i++) {
        int row = by * 128 + ty * 8 + i;
#pragma unroll
        for (int j = 0; j < 2; j++) {
            int col = bx * 128 + tx * 8 + j * 4;
            float a0, a1, a2, a3;
            unpack2(acc[i][j * 2 + 0], a0, a1);
            unpack2(acc[i][j * 2 + 1], a2, a3);
            float4 v;
            v.x = a0 + bias[col + 0];
            v.y = a1 + bias[col + 1];
            v.z = a2 + bias[col + 2];
            v.w = a3 + bias[col + 3];
            *(float4*)(C + (size_t)row * D_ + col) = v;
        }
    }
}

// Q and V projections fused in one launch: z=0 -> Wq->g_q, z=1 -> Wv->g_v
__global__ void __launch_bounds__(256, 2) gemm_qv_kernel(const float* __restrict__ Wq,
                                                         const float* __restrict__ bq,
                                                         const float* __restrict__ Wv,
                                                         const float* __restrict__ bv) {
    if (blockIdx.z == 0)
        gemm_core(g_x, Wq, bq, g_q, blockIdx.x, blockIdx.y);
    else
        gemm_core(g_x, Wv, bv, g_v, blockIdx.x, blockIdx.y);
}

// Wo projection: g_ao @ Wo + bo -> g_pr
__global__ void __launch_bounds__(256, 2) gemm_o_kernel(const float* __restrict__ Wo,
                                                        const float* __restrict__ bo) {
    gemm_core(g_ao, Wo, bo, g_pr, blockIdx.x, blockIdx.y);
}

// ---------------- scores: g_sc[bh][i][j] = dot(Qh_i, Qh_j)/8, lower tiles only ----
// 128x128 tile, 8x8 per thread, k=64 streamed as two 32-deep smem chunks.
__global__ void __launch_bounds__(256, 2) scores_kernel() {
    int jt = blockIdx.x;   // key tile (128 wide)
    int it = blockIdx.y;   // query tile (128 wide)
    int bh = blockIdx.z;
    if (jt > it) return;   // strictly-causal: only j <= i tiles needed

    int b = bh / H_, h = bh % H_;
    const float* Qb = g_q + (size_t)b * S_ * D_ + h * DH_;

    __shared__ float As[32][128];  // [k][i]
    __shared__ float Bs[32][128];  // [k][j]

    int tid = threadIdx.x;
    int tx = tid & 15, ty = tid >> 4;

    u64 acc[8][4];
#pragma unroll
    for (int i = 0; i < 8; i++)
#pragma unroll
        for (int j = 0; j < 4; j++) acc[i][j] = 0ull;

    float4 pa[4], pb[4];
    // preload chunk 0 (k = 0..31)
#pragma unroll
    for (int r = 0; r < 4; r++) {
        int g = tid + r * 256;
        pa[r] = *(const float4*)(Qb + (size_t)(it * 128 + (g >> 3)) * D_ + (g & 7) * 4);
        pb[r] = *(const float4*)(Qb + (size_t)(jt * 128 + (g >> 3)) * D_ + (g & 7) * 4);
    }
#pragma unroll
    for (int r = 0; r < 4; r++) {
        int g = tid + r * 256;
        int lr = g >> 3, lk = (g & 7) * 4;
        As[lk + 0][lr] = pa[r].x; As[lk + 1][lr] = pa[r].y;
        As[lk + 2][lr] = pa[r].z; As[lk + 3][lr] = pa[r].w;
        Bs[lk + 0][lr] = pb[r].x; Bs[lk + 1][lr] = pb[r].y;
        Bs[lk + 2][lr] = pb[r].z; Bs[lk + 3][lr] = pb[r].w;
    }
    __syncthreads();

#pragma unroll
    for (int c = 0; c < 2; c++) {
        if (c == 0) {
            // prefetch chunk 1 (k = 32..63)
#pragma unroll
            for (int r = 0; r < 4; r++) {
                int g = tid + r * 256;
                pa[r] = *(const float4*)(Qb + (size_t)(it * 128 + (g >> 3)) * D_ + 32 + (g & 7) * 4);
                pb[r] = *(const float4*)(Qb + (size_t)(jt * 128 + (g >> 3)) * D_ + 32 + (g & 7) * 4);
            }
        }
#pragma unroll
        for (int k = 0; k < 32; k++) {
            float4 ra0 = *(const float4*)&As[k][ty * 8];
            float4 ra1 = *(const float4*)&As[k][ty * 8 + 4];
            const u64* rbp = (const u64*)&Bs[k][tx * 8];
            u64 rb[4] = {rbp[0], rbp[1], rbp[2], rbp[3]};
            float ra[8] = {ra0.x, ra0.y, ra0.z, ra0.w, ra1.x, ra1.y, ra1.z, ra1.w};
#pragma unroll
            for (int i = 0; i < 8; i++) {
                u64 ad = pack2(ra[i], ra[i]);
#pragma unroll
                for (int j = 0; j < 4; j++) fma2(acc[i][j], ad, rb[j]);
            }
        }
        __syncthreads();
        if (c == 0) {
#pragma unroll
            for (int r = 0; r < 4; r++) {
                int g = tid + r * 256;
                int lr = g >> 3, lk = (g & 7) * 4;
                As[lk + 0][lr] = pa[r].x; As[lk + 1][lr] = pa[r].y;
                As[lk + 2][lr] = pa[r].z; As[lk + 3][lr] = pa[r].w;
                Bs[lk + 0][lr] = pb[r].x; Bs[lk + 1][lr] = pb[r].y;
                Bs[lk + 2][lr] = pb[r].z; Bs[lk + 3][lr] = pb[r].w;
            }
            __syncthreads();
        }
    }

    float* out = g_sc + (size_t)bh * S_ * S_;
#pragma unroll
    for (int i = 0; i < 8; i++) {
        int row = it * 128 + ty * 8 + i;
#pragma unroll
        for (int j = 0; j < 2; j++) {
            int col = jt * 128 + tx * 8 + j * 4;
            float a0, a1, a2, a3;
            unpack2(acc[i][j * 2 + 0], a0, a1);
            unpack2(acc[i][j * 2 + 1], a2, a3);
            float4 v = {a0 * 0.125f, a1 * 0.125f, a2 * 0.125f, a3 * 0.125f};
            *(float4*)(out + (size_t)row * S_ + col) = v;
        }
    }
}

// ---------------- per-row gamma-attention pipeline (warp per row) ----------------
// Each warp owns one (bh, q) row of 1024 scores. Thread owns contiguous 32-elem
// chunk (one 128B line). All reductions are shuffles; no __syncthreads.
// Fast-math transcendentals (__expf / sqrt.approx): rel-err budget 1e-3 >> 1e-5.
__global__ void __launch_bounds__(256) row_kernel(const float* __restrict__ gammas, int layer) {
    int warp = threadIdx.x >> 5, lane = threadIdx.x & 31;
    int q = blockIdx.x * 8 + warp;     // 0..1023
    int bh = blockIdx.y;
    int h = bh % H_;
    float* rowp = g_sc + (size_t)bh * S_ * S_ + (size_t)q * S_;
    float* chunk = rowp + lane * 32;

    if (q == 0) {                      // fully-masked row -> attn = 0
        float4 z = {0.f, 0.f, 0.f, 0.f};
#pragma unroll
        for (int i = 0; i < 8; i++) *(float4*)(chunk + i * 4) = z;
        return;
    }

    int kbase = lane * 32;
    float s[32];
#pragma unroll
    for (int i = 0; i < 8; i++) {
        float4 v = *(const float4*)(chunk + i * 4);
        s[i * 4 + 0] = v.x; s[i * 4 + 1] = v.y; s[i * 4 + 2] = v.z; s[i * 4 + 3] = v.w;
    }

    // ---- first masked softmax (unnormalized e, denom) ----
    float lmax = -INFINITY;
#pragma unroll
    for (int i = 0; i < 32; i++)
        if (kbase + i < q) lmax = fmaxf(lmax, s[i]);
    float m1 = warp_max(lmax);

    float e[32];
    float lsum = 0.f;
#pragma unroll
    for (int i = 0; i < 32; i++) {
        e[i] = (kbase + i < q) ? __expf(s[i] - m1) : 0.f;
        lsum += e[i];
    }
    float denom = warp_sum(lsum);
    float inv_denom = 1.0f / denom;

    // ---- inclusive cumsum of e across the row (local scan + warp offset) ----
    float incl = warp_iscan(lsum, lane);
    float excl = incl - lsum;
    float tot_e = __shfl_sync(0xffffffffu, incl, 31);
    float total = tot_e * inv_denom;   // == sum(p)

    // ---- distance decay + second softmax input ----
    float g = -fabsf(gammas[layer * H_ + h]);
    float run = excl;
    float dd = (float)(q - kbase);     // |q - k| for k < q; masked lanes don't care
    float lmax2 = -INFINITY;
#pragma unroll
    for (int i = 0; i < 32; i++) {
        run += e[i];
        float cum = run * inv_denom;                   // cumsum(p) inclusive
        float dist = sqrt_approx(fmaxf((total - cum) * dd, 0.f));
        dd -= 1.0f;
        float eff = __expf(dist * g);
        eff = fminf(fmaxf(eff, 1e-5f), 1e5f);
        float s2 = (kbase + i < q) ? s[i] * eff : -INFINITY;
        s[i] = s2;
        lmax2 = fmaxf(lmax2, s2);
    }
    float m2 = warp_max(lmax2);

    float lsum2 = 0.f;
#pragma unroll
    for (int i = 0; i < 32; i++) {
        e[i] = (kbase + i < q) ? __expf(s[i] - m2) : 0.f;
        lsum2 += e[i];
    }
    float d2 = warp_sum(lsum2);
    float inv_d2 = 1.0f / d2;

    // ---- maxout rescale: a = e/d2; scale = min(1/max(a), 5) ----
    float lamax = 0.f;
#pragma unroll
    for (int i = 0; i < 32; i++) lamax = fmaxf(lamax, e[i]);
    float amax = warp_max(lamax) * inv_d2;
    float scale = fminf(1.0f / amax, 5.0f) * inv_d2;

#pragma unroll
    for (int i = 0; i < 8; i++) {
        float4 v;
        v.x = e[i * 4 + 0] * scale;
        v.y = e[i * 4 + 1] * scale;
        v.z = e[i * 4 + 2] * scale;
        v.w = e[i * 4 + 3] * scale;
        *(float4*)(chunk + i * 4) = v;
    }
}

// ---------------- PV: g_ao[b, i, h*64+d] = sum_k attn[bh][i][k] * Vh[k][d] --------
// Register double-buffered over kt tiles.
__global__ void __launch_bounds__(256, 2) pv_kernel() {
    int it = blockIdx.x;   // query row tile (16)
    int bh = blockIdx.y;
    int b = bh / H_, h = bh % H_;
    const float* att = g_sc + (size_t)bh * S_ * S_;
    const float* Vb = g_v + (size_t)b * S_ * D_ + h * DH_;
    float* Ob = g_ao + (size_t)b * S_ * D_ + h * DH_;

    __shared__ float As[64][64];  // attn transposed: [k][i]
    __shared__ float Bs[64][64];  // V: [k][d]

    int tid = threadIdx.x, tx = tid & 15, ty = tid >> 4;

    // load coordinates: 4 float4 per tile per array
    int lrow[4], lcq[4];
#pragma unroll
    for (int r = 0; r < 4; r++) {
        int g = tid + r * 256;
        lrow[r] = g >> 4;      // 0..63
        lcq[r] = (g & 15) * 4; // col offset
    }

    u64 acc[4][2];
#pragma unroll
    for (int i = 0; i < 4; i++) { acc[i][0] = 0ull; acc[i][1] = 0ull; }

    float4 va[4], vb[4];
    // preload kt = 0
#pragma unroll
    for (int r = 0; r < 4; r++) {
        va[r] = *(const float4*)(att + (size_t)(it * 64 + lrow[r]) * S_ + lcq[r]);
        vb[r] = *(const float4*)(Vb + (size_t)lrow[r] * D_ + lcq[r]);
    }
#pragma unroll
    for (int r = 0; r < 4; r++) {
        As[lcq[r] + 0][lrow[r]] = va[r].x; As[lcq[r] + 1][lrow[r]] = va[r].y;
        As[lcq[r] + 2][lrow[r]] = va[r].z; As[lcq[r] + 3][lrow[r]] = va[r].w;
        *(float4*)&Bs[lrow[r]][lcq[r]] = vb[r];
    }
    __syncthreads();

    // causal: attn[i][k]==0 for k > i, so only chunks kt <= it contribute
    for (int kt = 0; kt <= it; kt++) {
        if (kt + 1 <= it) {
#pragma unroll
            for (int r = 0; r < 4; r++) {
                va[r] = *(const float4*)(att + (size_t)(it * 64 + lrow[r]) * S_ + (kt + 1) * 64 + lcq[r]);
                vb[r] = *(const float4*)(Vb + (size_t)((kt + 1) * 64 + lrow[r]) * D_ + lcq[r]);
            }
        }
#pragma unroll 8
        for (int k = 0; k < 64; k++) {
            float4 ra = *(const float4*)&As[k][ty * 4];
            const u64* rbp = (const u64*)&Bs[k][tx * 4];
            u64 rb0 = rbp[0], rb1 = rbp[1];
            float rav[4] = {ra.x, ra.y, ra.z, ra.w};
#pragma unroll
            for (int i = 0; i < 4; i++) {
                u64 ad = pack2(rav[i], rav[i]);
                fma2(acc[i][0], ad, rb0);
                fma2(acc[i][1], ad, rb1);
            }
        }
        __syncthreads();
        if (kt + 1 <= it) {
#pragma unroll
            for (int r = 0; r < 4; r++) {
                As[lcq[r] + 0][lrow[r]] = va[r].x; As[lcq[r] + 1][lrow[r]] = va[r].y;
                As[lcq[r] + 2][lrow[r]] = va[r].z; As[lcq[r] + 3][lrow[r]] = va[r].w;
                *(float4*)&Bs[lrow[r]][lcq[r]] = vb[r];
            }
            __syncthreads();
        }
    }

#pragma unroll
    for (int i = 0; i < 4; i++) {
        float a0, a1, a2, a3;
        unpack2(acc[i][0], a0, a1);
        unpack2(acc[i][1], a2, a3);
        float4 v = {a0, a1, a2, a3};
        *(float4*)(Ob + (size_t)(it * 64 + ty * 4 + i) * D_ + tx * 4) = v;
    }
}

// ---------------- (x [+ g_pr]) -> LayerNorm -> (g_x | out) ----------------
// addA=1: v = g_x + g_pr, write g_x.  addA=0: v = g_x, write `out`.
__global__ void __launch_bounds__(256) ln_kernel(const float* __restrict__ gw,
                                                 const float* __restrict__ bw,
                                                 float* __restrict__ out, int addA) {
    int row = blockIdx.x;
    int t = threadIdx.x;
    int lane = t & 31, wid = t >> 5;
    __shared__ float red[33];

    float4 xv = *(const float4*)(g_x + (size_t)row * D_ + t * 4);
    float v0 = xv.x, v1 = xv.y, v2 = xv.z, v3 = xv.w;
    if (addA) {
        float4 av = *(const float4*)(g_pr + (size_t)row * D_ + t * 4);
        v0 += av.x; v1 += av.y; v2 += av.z; v3 += av.w;
    }
    float ssum = warp_sum(v0 + v1 + v2 + v3);
    if (lane == 0) red[wid] = ssum;
    __syncthreads();
    if (wid == 0) {
        float u = (lane < 8) ? red[lane] : 0.0f;
        u = warp_sum(u);
        if (lane == 0) red[32] = u;
    }
    __syncthreads();
    float mu = red[32] * (1.0f / D_);
    __syncthreads();

    float d0 = v0 - mu, d1 = v1 - mu, d2 = v2 - mu, d3 = v3 - mu;
    float vs = warp_sum(d0 * d0 + d1 * d1 + d2 * d2 + d3 * d3);
    if (lane == 0) red[wid] = vs;
    __syncthreads();
    if (wid == 0) {
        float u = (lane < 8) ? red[lane] : 0.0f;
        u = warp_sum(u);
        if (lane == 0) red[32] = u;
    }
    __syncthreads();
    float var = red[32] * (1.0f / D_);
    float rs = rsqrtf(var + 1e-5f);

    float4 g4 = *(const float4*)(gw + t * 4);
    float4 b4 = *(const float4*)(bw + t * 4);
    float4 o;
    o.x = d0 * rs * g4.x + b4.x;
    o.y = d1 * rs * g4.y + b4.y;
    o.z = d2 * rs * g4.z + b4.z;
    o.w = d3 * rs * g4.w + b4.w;
    float* dst = addA ? g_x : out;
    *(float4*)(dst + (size_t)row * D_ + t * 4) = o;
}

// ---------------- launch ----------------
extern "C" void kernel_launch(void* const* d_in, const int* in_sizes, int n_in,
                              void* d_out, int out_size) {
    (void)in_sizes; (void)n_in; (void)out_size;
    const float* q      = (const float*)d_in[0];
    // d_in[1] = lens (unused in eval mode)
    const float* Wq     = (const float*)d_in[2];
    const float* bq     = (const float*)d_in[3];
    const float* Wv     = (const float*)d_in[4];
    const float* bv     = (const float*)d_in[5];
    const float* Wo     = (const float*)d_in[6];
    const float* bo     = (const float*)d_in[7];
    const float* gammas = (const float*)d_in[8];
    const float* ln_g   = (const float*)d_in[9];
    const float* ln_b   = (const float*)d_in[10];
    const float* fin_g  = (const float*)d_in[11];
    const float* fin_b  = (const float*)d_in[12];

    // x = q
    copy_in_kernel<<<(M_ * D_ / 4) / 256, 256>>>((const float4*)q);

    dim3 qv_grid(D_ / 128, M_ / 128, 2);    // (8, 16, 2)
    dim3 o_grid(D_ / 128, M_ / 128);        // (8, 16)
    for (int l = 0; l < L_; l++) {
        size_t wOff = (size_t)l * D_ * D_;
        gemm_qv_kernel<<<qv_grid, 256>>>(Wq + wOff, bq + (size_t)l * D_,
                                         Wv + wOff, bv + (size_t)l * D_);
        scores_kernel<<<dim3(S_ / 128, S_ / 128, BH_), 256>>>();
        row_kernel<<<dim3(S_ / 8, BH_), 256>>>(gammas, l);
        pv_kernel<<<dim3(S_ / 64, BH_), 256>>>();
        gemm_o_kernel<<<o_grid, 256>>>(Wo + wOff, bo + (size_t)l * D_);
        ln_kernel<<<M_, 256>>>(ln_g + (size_t)l * D_, ln_b + (size_t)l * D_, nullptr, 1);
    }
    // final layer norm -> output
    ln_kernel<<<M_, 256>>>(fin_g, fin_b, (float*)d_out, 0);
}